// round 16
// baseline (speedup 1.0000x reference)
#include <cuda_runtime.h>

#define NEXP 5
#define HID  20
#define NP   10   // hidden-unit pairs per expert
#define TPT  4    // tokens per thread

typedef unsigned long long ull;

__device__ __forceinline__ ull pack2(float lo, float hi) {
    ull r;
    asm("mov.b64 %0, {%1, %2};" : "=l"(r) : "f"(lo), "f"(hi));
    return r;
}
__device__ __forceinline__ void unpack2(ull v, float& lo, float& hi) {
    asm("mov.b64 {%0, %1}, %2;" : "=f"(lo), "=f"(hi) : "l"(v));
}
__device__ __forceinline__ ull fma2(ull a, ull b, ull c) {
    ull r;
    asm("fma.rn.f32x2 %0, %1, %2, %3;" : "=l"(r) : "l"(a), "l"(b), "l"(c));
    return r;
}
__device__ __forceinline__ ull relu2(ull v) {
    float lo, hi;
    unpack2(v, lo, hi);               // register-half naming: elides
    return pack2(fmaxf(lo, 0.0f), fmaxf(hi, 0.0f));  // 2x FMNMX
}

// Packed weights in the __constant__ bank (LDC path — the only cheap
// broadcast port, measured vs LDS (R11) and uniform LDG (R12)).
// prep_kernel writes DIRECTLY into the constant bank's backing storage;
// the main kernel is launched with Programmatic Dependent Launch and does
// griddepcontrol.wait before its first constant read, so its grid launch
// overlaps prep's execution.
struct CW {
    ulonglong2 w1a[NEXP * NP];  // {w1x2, w1y2}
    ulonglong2 w1b[NEXP * NP];  // {w1z2, b1_2}
    ulonglong2 w2a[NEXP * NP];  // {w2x2, w2y2}
    ull        w2z[NEXP * NP];  // w2z2
    ull        gw[NEXP * 2];    // per e: {Wg0,Wg1}, {Wg2,bg}
    ull        b2d[NEXP * 3];   // per (e,o): {b2[e,o], 0}
};

__constant__ CW c_w;

__global__ void prep_kernel(CW* __restrict__ cw,
                            const float* __restrict__ W1, const float* __restrict__ b1,
                            const float* __restrict__ W2, const float* __restrict__ b2,
                            const float* __restrict__ Wg, const float* __restrict__ bg)
{
    int t = threadIdx.x;
    if (t < NEXP * NP) {
        int e = t / NP, i = t % NP, h = 2 * i;
        const float* w1e = W1 + e * 3 * HID;
        cw->w1a[t] = make_ulonglong2(pack2(w1e[0 * HID + h], w1e[0 * HID + h + 1]),
                                     pack2(w1e[1 * HID + h], w1e[1 * HID + h + 1]));
        cw->w1b[t] = make_ulonglong2(pack2(w1e[2 * HID + h], w1e[2 * HID + h + 1]),
                                     pack2(b1[e * HID + h], b1[e * HID + h + 1]));
        const float* w2e = W2 + e * HID * 3;
        cw->w2a[t] = make_ulonglong2(pack2(w2e[h * 3 + 0], w2e[(h + 1) * 3 + 0]),
                                     pack2(w2e[h * 3 + 1], w2e[(h + 1) * 3 + 1]));
        cw->w2z[t] = pack2(w2e[h * 3 + 2], w2e[(h + 1) * 3 + 2]);
    } else if (t < NEXP * NP + NEXP) {
        int e = t - NEXP * NP;
        cw->gw[e * 2 + 0] = pack2(Wg[0 * NEXP + e], Wg[1 * NEXP + e]);
        cw->gw[e * 2 + 1] = pack2(Wg[2 * NEXP + e], bg[e]);
        cw->b2d[e * 3 + 0] = pack2(b2[e * 3 + 0], 0.0f);
        cw->b2d[e * 3 + 1] = pack2(b2[e * 3 + 1], 0.0f);
        cw->b2d[e * 3 + 2] = pack2(b2[e * 3 + 2], 0.0f);
    }
}

__global__ __launch_bounds__(256, 3) void moe_kernel(
    const float* __restrict__ x,
    float* __restrict__ out_mixed, float* __restrict__ out_gate,
    int ngroups)
{
    int gid = blockIdx.x * blockDim.x + threadIdx.x;  // group of 4 tokens
    if (gid >= ngroups) return;

    // ---- Load 4 tokens' x (independent of prep: issue before the PDL wait) ----
    const float4* x4 = (const float4*)x;
    float4 xa = x4[3 * gid + 0];
    float4 xb = x4[3 * gid + 1];
    float4 xc = x4[3 * gid + 2];

    // PDL: wait for prep_kernel's completion/flush before first constant read.
    asm volatile("griddepcontrol.wait;" ::: "memory");

    float x0s[4] = {xa.x, xa.w, xb.z, xc.y};
    float x1s[4] = {xa.y, xb.x, xb.w, xc.z};
    float x2s[4] = {xa.z, xb.y, xc.x, xc.w};

    // ---- Gate: logits + softmax (no max-subtraction: logits bounded) ----
    float g[TPT][NEXP];
    #pragma unroll
    for (int e = 0; e < NEXP; e++) {
        float wx, wy, wz, bgv;
        unpack2(c_w.gw[e * 2 + 0], wx, wy);
        unpack2(c_w.gw[e * 2 + 1], wz, bgv);
        #pragma unroll
        for (int k = 0; k < TPT; k++)
            g[k][e] = fmaf(x0s[k], wx, fmaf(x1s[k], wy, fmaf(x2s[k], wz, bgv)));
    }
    #pragma unroll
    for (int k = 0; k < TPT; k++) {
        float s = 0.0f;
        #pragma unroll
        for (int e = 0; e < NEXP; e++) { g[k][e] = __expf(g[k][e]); s += g[k][e]; }
        float inv = __fdividef(1.0f, s);
        #pragma unroll
        for (int e = 0; e < NEXP; e++) g[k][e] *= inv;
    }

    // Store gate output (20 floats = 5x STG.128).
    float4* og = (float4*)out_gate;
    og[5 * gid + 0] = make_float4(g[0][0], g[0][1], g[0][2], g[0][3]);
    og[5 * gid + 1] = make_float4(g[0][4], g[1][0], g[1][1], g[1][2]);
    og[5 * gid + 2] = make_float4(g[1][3], g[1][4], g[2][0], g[2][1]);
    og[5 * gid + 3] = make_float4(g[2][2], g[2][3], g[2][4], g[3][0]);
    og[5 * gid + 4] = make_float4(g[3][1], g[3][2], g[3][3], g[3][4]);

    // Broadcast-packed x (12 packs/thread).
    ull xd0[TPT], xd1[TPT], xd2[TPT];
    #pragma unroll
    for (int k = 0; k < TPT; k++) {
        xd0[k] = pack2(x0s[k], x0s[k]);
        xd1[k] = pack2(x1s[k], x1s[k]);
        xd2[k] = pack2(x2s[k], x2s[k]);
    }

    // ---- Experts: fc1 + ReLU + fc2 via uniform constant loads ----
    float mix0[TPT] = {0.f, 0.f, 0.f, 0.f};
    float mix1[TPT] = {0.f, 0.f, 0.f, 0.f};
    float mix2[TPT] = {0.f, 0.f, 0.f, 0.f};

    #pragma unroll
    for (int e = 0; e < NEXP; e++) {
        ull bb0 = c_w.b2d[e * 3 + 0];
        ull bb1 = c_w.b2d[e * 3 + 1];
        ull bb2 = c_w.b2d[e * 3 + 2];
        ull acc0[TPT], acc1[TPT], acc2[TPT];
        #pragma unroll
        for (int k = 0; k < TPT; k++) { acc0[k] = bb0; acc1[k] = bb1; acc2[k] = bb2; }

        #pragma unroll
        for (int i = 0; i < NP; i++) {
            int idx = e * NP + i;                 // immediate after unroll
            ulonglong2 w1a = c_w.w1a[idx];        // uniform .128
            ulonglong2 w1b = c_w.w1b[idx];        // uniform .128
            ulonglong2 w2a = c_w.w2a[idx];        // uniform .128
            ull        w2z = c_w.w2z[idx];        // uniform .64
            #pragma unroll
            for (int k = 0; k < TPT; k++) {
                ull hv = fma2(xd0[k], w1a.x, fma2(xd1[k], w1a.y, fma2(xd2[k], w1b.x, w1b.y)));
                hv = relu2(hv);
                acc0[k] = fma2(hv, w2a.x, acc0[k]);
                acc1[k] = fma2(hv, w2a.y, acc1[k]);
                acc2[k] = fma2(hv, w2z,  acc2[k]);
            }
        }
        #pragma unroll
        for (int k = 0; k < TPT; k++) {
            float lo, hi, ge = g[k][e];
            unpack2(acc0[k], lo, hi); mix0[k] = fmaf(ge, lo + hi, mix0[k]);
            unpack2(acc1[k], lo, hi); mix1[k] = fmaf(ge, lo + hi, mix1[k]);
            unpack2(acc2[k], lo, hi); mix2[k] = fmaf(ge, lo + hi, mix2[k]);
        }
    }

    // ---- Store mixed (12 floats = 3x STG.128) ----
    float4* om = (float4*)out_mixed;
    om[3 * gid + 0] = make_float4(mix0[0], mix1[0], mix2[0], mix0[1]);
    om[3 * gid + 1] = make_float4(mix1[1], mix2[1], mix0[2], mix1[2]);
    om[3 * gid + 2] = make_float4(mix2[2], mix0[3], mix1[3], mix2[3]);
}

extern "C" void kernel_launch(void* const* d_in, const int* in_sizes, int n_in,
                              void* d_out, int out_size)
{
    // Input order per setup_inputs: x, W1, b1, W2, b2, Wg, bg
    const float* x  = (const float*)d_in[0];
    const float* W1 = (const float*)d_in[1];
    const float* b1 = (const float*)d_in[2];
    const float* W2 = (const float*)d_in[3];
    const float* b2 = (const float*)d_in[4];
    const float* Wg = (const float*)d_in[5];
    const float* bg = (const float*)d_in[6];

    int B = in_sizes[0] / 3;           // x is [B, 3]
    int ngroups = B / TPT;             // 4 tokens per thread

    float* out_mixed = (float*)d_out;            // [B, 3]
    float* out_gate  = (float*)d_out + 3 * B;    // [B, 5]

    // 1) pack weights directly into the constant bank's backing storage.
    void* cw_ptr = nullptr;
    cudaGetSymbolAddress(&cw_ptr, c_w);
    prep_kernel<<<1, 64>>>((CW*)cw_ptr, W1, b1, W2, b2, Wg, bg);

    // 2) main kernel with Programmatic Dependent Launch: its launch overlaps
    //    prep's execution; device-side griddepcontrol.wait orders the
    //    constant reads after prep's writes.
    int threads = 256;
    int blocks = (ngroups + threads - 1) / threads;

    cudaLaunchConfig_t cfg = {};
    cfg.gridDim  = dim3(blocks, 1, 1);
    cfg.blockDim = dim3(threads, 1, 1);
    cfg.dynamicSmemBytes = 0;
    cfg.stream = 0;   // legacy default stream (the captured stream)
    cudaLaunchAttribute attrs[1];
    attrs[0].id = cudaLaunchAttributeProgrammaticStreamSerialization;
    attrs[0].val.programmaticStreamSerializationAllowed = 1;
    cfg.attrs = attrs;
    cfg.numAttrs = 1;

    cudaLaunchKernelEx(&cfg, moe_kernel, x, out_mixed, out_gate, ngroups);
}